// round 2
// baseline (speedup 1.0000x reference)
#include <cuda_runtime.h>
#include <cuda_bf16.h>

// QuantumFeatureMap: RY(1.57*x_q) per qubit + CNOT ring + diagonal Z observables.
// Closed form via GF(2) parity pullback of the CNOT ring, with t_q = cos(1.57*x_q):
//
//   final bits: m0=B1^B2^B3, m1=B0^B1, m2=B0^B1^B2, m3=B0^B1^B2^B3
//
//   out0 = t1*t2*t3        (Z0)
//   out1 = t0*t1           (Z1)
//   out2 = t0*t1*t2        (Z2)
//   out3 = t0*t1*t2*t3     (Z3)
//   out4 = t0*t2*t3        (Z0Z1)
//   out5 = t0*t3           (Z0Z2)
//   out6 = t0              (Z0Z3)   <- m0^m3 = B0 (was wrongly t0*t2 in R0)
//   out7 = t2              (Z1Z2)
//   out8 = t2*t3           (Z1Z3)
//   out9 = t3              (Z2Z3)

#define QFM_ALPHA 1.57f
#define QFM_BLOCK 256

__global__ void __launch_bounds__(QFM_BLOCK)
qfm_kernel(const float4* __restrict__ x, float4* __restrict__ out)
{
    __shared__ __align__(16) float s[QFM_BLOCK * 10];

    const int tid = threadIdx.x;
    const int row = blockIdx.x * QFM_BLOCK + tid;

    // One float4 per row: the 4 qubit angles. Coalesced 16B loads.
    float4 v = x[row];

    float t0 = __cosf(QFM_ALPHA * v.x);
    float t1 = __cosf(QFM_ALPHA * v.y);
    float t2 = __cosf(QFM_ALPHA * v.z);
    float t3 = __cosf(QFM_ALPHA * v.w);

    float t01 = t0 * t1;
    float t23 = t2 * t3;

    float* p = s + tid * 10;
    p[0] = t1 * t23;
    p[1] = t01;
    p[2] = t01 * t2;
    p[3] = t01 * t23;
    p[4] = t0 * t23;
    p[5] = t0 * t3;
    p[6] = t0;
    p[7] = t2;
    p[8] = t23;
    p[9] = t3;

    __syncthreads();

    // Block's output region: QFM_BLOCK rows * 10 floats = 2560 floats = 640 float4.
    // 640*16 = 10240 bytes per block, 16B-aligned -> fully coalesced STG.128.
    const float4* s4 = (const float4*)s;
    float4* o = out + (size_t)blockIdx.x * (QFM_BLOCK * 10 / 4);

    #pragma unroll
    for (int i = tid; i < QFM_BLOCK * 10 / 4; i += QFM_BLOCK)
        o[i] = s4[i];
}

extern "C" void kernel_launch(void* const* d_in, const int* in_sizes, int n_in,
                              void* d_out, int out_size)
{
    const float4* x = (const float4*)d_in[0];
    float4* out = (float4*)d_out;

    const int n_rows = in_sizes[0] / 4;          // [B,4] float32
    const int grid = n_rows / QFM_BLOCK;         // B = 1048576 -> 4096 blocks

    qfm_kernel<<<grid, QFM_BLOCK>>>(x, out);
}